// round 4
// baseline (speedup 1.0000x reference)
#include <cuda_runtime.h>

#define BSZ   8
#define NNODE 20000
#define FIN   256
#define NH    8
#define ND    64
#define EDG   160000
#define NJ    16   // 8 src heads + 8 trg heads

// Scratch (static __device__ — no allocation allowed).
// __align__(16): accessed via 16B vector loads.
__device__ __align__(16) float g_w[BSZ * NJ * FIN];         // 128 KB effective weights
__device__ __align__(16) float g_scores[BSZ * NNODE * NJ];  // 20.48 MB per-node scores

// ---------------------------------------------------------------------------
// Kernel 1: fold scoring vectors into the projection ->
//   g_w[b][j][f] = sum_d W[(h*64+d)*256+f] * s[b][h][d],  h=j&7, s=src if j<8 else trg
// ---------------------------------------------------------------------------
__global__ void build_w_kernel(const float* __restrict__ W,
                               const float* __restrict__ ssrc,
                               const float* __restrict__ strg) {
    const int f  = threadIdx.x;      // 0..255
    const int bj = blockIdx.x;       // 0..127
    const int b  = bj >> 4;
    const int j  = bj & 15;
    const int h  = j & 7;
    const float* __restrict__ s = (j < 8 ? ssrc : strg) + (b * NH + h) * ND;
    float acc = 0.f;
#pragma unroll 8
    for (int d = 0; d < ND; ++d)
        acc += W[(h * ND + d) * FIN + f] * s[d];
    g_w[bj * FIN + f] = acc;
}

// ---------------------------------------------------------------------------
// Kernel 2: per-node scoring.  One warp per node row.
//   scores[b][n][j] = dot(x[b][n][:], g_w[b][j][:])   (j = 16 outputs)
// Weights in registers, packed f32x2 FMA, 16-shuffle butterfly reduction.
// ---------------------------------------------------------------------------
__device__ __forceinline__ void ffma2(unsigned long long& acc,
                                      unsigned long long a,
                                      unsigned long long b) {
    asm("fma.rn.f32x2 %0, %1, %2, %0;" : "+l"(acc) : "l"(a), "l"(b));
}

__global__ __launch_bounds__(256, 1)
void score_kernel(const float* __restrict__ x) {
    const int b       = blockIdx.y;
    const int lane    = threadIdx.x & 31;
    const int warp    = threadIdx.x >> 5;
    const int wstride = gridDim.x * 8;
    const int n0      = blockIdx.x * 8 + warp;

    // Weights for this batch: lane covers f in [4*lane,4*lane+4) and [128+4*lane, +4)
    const ulonglong2* __restrict__ Wv =
        reinterpret_cast<const ulonglong2*>(g_w) + (size_t)b * NJ * (FIN / 4);
    ulonglong2 wA[NJ], wB[NJ];
#pragma unroll
    for (int j = 0; j < NJ; ++j) {
        wA[j] = Wv[j * 64 + lane];
        wB[j] = Wv[j * 64 + 32 + lane];
    }

    const ulonglong2* __restrict__ Xv =
        reinterpret_cast<const ulonglong2*>(x) + (size_t)b * NNODE * 64;

    // Depth-2 prefetch pipeline over rows
    ulonglong2 bufA[2], bufB[2];
    int n_pre = n0;
#pragma unroll
    for (int p = 0; p < 2; ++p) {
        if (n_pre < NNODE) {
            bufA[p] = Xv[(size_t)n_pre * 64 + lane];
            bufB[p] = Xv[(size_t)n_pre * 64 + 32 + lane];
        }
        n_pre += wstride;
    }

    int slot = 0;
    for (int n = n0; n < NNODE; n += wstride) {
        const ulonglong2 xA = bufA[slot];
        const ulonglong2 xB = bufB[slot];
        if (n_pre < NNODE) {
            bufA[slot] = Xv[(size_t)n_pre * 64 + lane];
            bufB[slot] = Xv[(size_t)n_pre * 64 + 32 + lane];
        }
        n_pre += wstride;
        slot ^= 1;

        unsigned long long acc[NJ];
#pragma unroll
        for (int j = 0; j < NJ; ++j) {
            acc[j] = 0ull;
            ffma2(acc[j], xA.x, wA[j].x);
            ffma2(acc[j], xA.y, wA[j].y);
            ffma2(acc[j], xB.x, wB[j].x);
            ffma2(acc[j], xB.y, wB[j].y);
        }

        // collapse each f32x2 pair
        float v[NJ];
#pragma unroll
        for (int j = 0; j < NJ; ++j) {
            float lo, hi;
            asm("mov.b64 {%0, %1}, %2;" : "=f"(lo), "=f"(hi) : "l"(acc[j]));
            v[j] = lo + hi;
        }

        // accumulator-halving butterfly: 16 shuffles total.
        // End state: lane 2j (even lanes) holds fully-reduced output j.
        {
            const bool h4 = (lane & 16) != 0;
#pragma unroll
            for (int k = 0; k < 8; ++k) {
                float send = h4 ? v[k] : v[8 + k];
                float recv = __shfl_xor_sync(0xffffffffu, send, 16);
                v[k] = (h4 ? v[8 + k] : v[k]) + recv;
            }
            const bool h3 = (lane & 8) != 0;
#pragma unroll
            for (int k = 0; k < 4; ++k) {
                float send = h3 ? v[k] : v[4 + k];
                float recv = __shfl_xor_sync(0xffffffffu, send, 8);
                v[k] = (h3 ? v[4 + k] : v[k]) + recv;
            }
            const bool h2 = (lane & 4) != 0;
#pragma unroll
            for (int k = 0; k < 2; ++k) {
                float send = h2 ? v[k] : v[2 + k];
                float recv = __shfl_xor_sync(0xffffffffu, send, 4);
                v[k] = (h2 ? v[2 + k] : v[k]) + recv;
            }
            const bool h1 = (lane & 2) != 0;
            {
                float send = h1 ? v[0] : v[1];
                float recv = __shfl_xor_sync(0xffffffffu, send, 2);
                v[0] = (h1 ? v[1] : v[0]) + recv;
            }
            v[0] += __shfl_xor_sync(0xffffffffu, v[0], 1);
        }

        if ((lane & 1) == 0) {
            const int j = lane >> 1;
            g_scores[((size_t)b * NNODE + n) * NJ + j] = v[0];
        }
    }
}

// ---------------------------------------------------------------------------
// Kernel 3: edge gather + sigmoid.  Indices are INT32 (JAX default x64=off
// downcasts int64 -> int32).  flat idx in [0, bsz*N*H); node = idx>>3, h = idx&7.
//   src score at g_scores[node*16 + h], trg at g_scores[node*16 + 8 + h].
// ---------------------------------------------------------------------------
__global__ void gather_kernel(const int* __restrict__ head,
                              const int* __restrict__ tail,
                              float* __restrict__ out, int total) {
    const int i = blockIdx.x * blockDim.x + threadIdx.x;
    if (i >= total) return;
    const int hidx = head[i];
    const int tidx = tail[i];
    const int hn = hidx >> 3;
    const int hh = hidx & 7;
    const int tn = tidx >> 3;
    const int th = tidx & 7;
    const float s = g_scores[(size_t)hn * NJ + hh] +
                    g_scores[(size_t)tn * NJ + 8 + th];
    out[i] = 1.0f / (1.0f + __expf(-s));
}

// ---------------------------------------------------------------------------
extern "C" void kernel_launch(void* const* d_in, const int* in_sizes, int n_in,
                              void* d_out, int out_size) {
    // Classify inputs by element count — robust to metadata ordering.
    //   40,960,000 -> concept_hidden (f32)
    //      131,072 -> W_proj (f32)
    //    1,280,000 -> head (first seen), tail (second)  [int32]
    //        4,096 -> scoring_src (first seen), scoring_trg (second)  [f32]
    const float* x    = nullptr;
    const float* W    = nullptr;
    const int*   head = nullptr;
    const int*   tail = nullptr;
    const float* ssrc = nullptr;
    const float* strg = nullptr;
    for (int i = 0; i < n_in; ++i) {
        const int sz = in_sizes[i];
        if (sz == BSZ * NNODE * FIN) {
            x = (const float*)d_in[i];
        } else if (sz == NH * ND * FIN) {
            W = (const float*)d_in[i];
        } else if (sz == BSZ * EDG) {
            if (!head) head = (const int*)d_in[i];
            else       tail = (const int*)d_in[i];
        } else if (sz == BSZ * NH * ND) {
            if (!ssrc) ssrc = (const float*)d_in[i];
            else       strg = (const float*)d_in[i];
        }
    }
    float* out = (float*)d_out;  // [8,160000] f32

    build_w_kernel<<<BSZ * NJ, FIN>>>(W, ssrc, strg);

    dim3 g2(19, BSZ);                 // 152 blocks ~ one wave of 148 SMs
    score_kernel<<<g2, 256>>>(x);

    const int total = BSZ * EDG;
    gather_kernel<<<(total + 255) / 256, 256>>>(head, tail, out, total);
}

// round 6
// speedup vs baseline: 1.6232x; 1.6232x over previous
#include <cuda_runtime.h>

#define BSZ   8
#define NNODE 20000
#define FIN   256
#define NH    8
#define ND    64
#define EDG   160000
#define NJ    16   // 8 src heads + 8 trg heads

__device__ __align__(16) float g_w[BSZ * NJ * FIN];         // 128 KB effective weights
__device__ __align__(16) float g_scores[BSZ * NNODE * NJ];  // 20.48 MB per-node scores

// ---------------------------------------------------------------------------
// Kernel 1: fold scoring vectors into projection weights.
//   g_w[b][j][f] = sum_d W[(h*64+d)*256+f] * s[b][h][d]
// 8 independent accumulators + full unroll -> 64 loads in flight (MLP-bound).
// ---------------------------------------------------------------------------
__global__ void build_w_kernel(const float* __restrict__ W,
                               const float* __restrict__ ssrc,
                               const float* __restrict__ strg) {
    const int f  = threadIdx.x;      // 0..255
    const int bj = blockIdx.x;       // 0..127
    const int b  = bj >> 4;
    const int j  = bj & 15;
    const int h  = j & 7;
    const float* __restrict__ s = (j < 8 ? ssrc : strg) + (b * NH + h) * ND;
    const float* __restrict__ Wh = W + h * ND * FIN + f;
    float acc[8] = {0.f, 0.f, 0.f, 0.f, 0.f, 0.f, 0.f, 0.f};
#pragma unroll
    for (int d = 0; d < ND; ++d)
        acc[d & 7] += Wh[d * FIN] * __ldg(&s[d]);
    float t0 = (acc[0] + acc[1]) + (acc[2] + acc[3]);
    float t1 = (acc[4] + acc[5]) + (acc[6] + acc[7]);
    g_w[bj * FIN + f] = t0 + t1;
}

// ---------------------------------------------------------------------------
// Kernel 2: per-node scoring.  One warp per row; weights register-resident.
// f32x2 FMAs; reduction: 4 accumulator-halving u64 butterfly stages + xor1 +
// lo/hi collapse (all adds are add.rn.f32x2 / 1 final FADD).
// Ping-pong prefetch with COMPILE-TIME slot indices (no local-memory demotion).
// ---------------------------------------------------------------------------
__device__ __forceinline__ void ffma2(unsigned long long& acc,
                                      unsigned long long a,
                                      unsigned long long b) {
    asm("fma.rn.f32x2 %0, %1, %2, %0;" : "+l"(acc) : "l"(a), "l"(b));
}
__device__ __forceinline__ unsigned long long add2(unsigned long long a,
                                                   unsigned long long b) {
    unsigned long long r;
    asm("add.rn.f32x2 %0, %1, %2;" : "=l"(r) : "l"(a), "l"(b));
    return r;
}

#define CHUNK 140   // 144 warps/batch * 140 = 20160 >= 20000; CHUNK % 4 == 0

__global__ __launch_bounds__(256, 1)
void score_kernel(const float* __restrict__ x) {
    const int b     = blockIdx.y;
    const int lane  = threadIdx.x & 31;
    const int warp  = threadIdx.x >> 5;
    const int nbeg  = (blockIdx.x * 8 + warp) * CHUNK;

    // Weights: lane covers f in [4*lane,4*lane+4) and [128+4*lane,+4)
    const ulonglong2* __restrict__ Wv =
        reinterpret_cast<const ulonglong2*>(g_w) + (size_t)b * NJ * (FIN / 4);
    ulonglong2 wA[NJ], wB[NJ];
#pragma unroll
    for (int j = 0; j < NJ; ++j) {
        wA[j] = Wv[j * 64 + lane];
        wB[j] = Wv[j * 64 + 32 + lane];
    }

    const ulonglong2* __restrict__ Xv =
        reinterpret_cast<const ulonglong2*>(x) + (size_t)b * NNODE * 64;

    // [slot][row-in-pair] — every index is a literal after unrolling.
    ulonglong2 xA[2][2], xB[2][2];

#define LOADROW(n, dstA, dstB)                                        \
    do {                                                              \
        if ((n) < NNODE) {                                            \
            dstA = __ldcs(&Xv[(size_t)(n) * 64 + lane]);              \
            dstB = __ldcs(&Xv[(size_t)(n) * 64 + 32 + lane]);         \
        } else {                                                      \
            dstA.x = dstA.y = 0ull; dstB.x = dstB.y = 0ull;           \
        }                                                             \
    } while (0)

    // Prologue: pair 0 into slot 0.
    LOADROW(nbeg,     xA[0][0], xB[0][0]);
    LOADROW(nbeg + 1, xA[0][1], xB[0][1]);

    float* __restrict__ gs = g_scores + (size_t)b * NNODE * NJ;

    for (int i = 0; i < CHUNK / 4; ++i) {
#pragma unroll
        for (int u = 0; u < 2; ++u) {
            const int base = nbeg + i * 4 + u * 2;
            // Prefetch next pair into the other slot (consumed one pair later).
            LOADROW(base + 2, xA[u ^ 1][0], xB[u ^ 1][0]);
            LOADROW(base + 3, xA[u ^ 1][1], xB[u ^ 1][1]);

#pragma unroll
            for (int r = 0; r < 2; ++r) {
                const int n = base + r;
                const ulonglong2 a = xA[u][r];
                const ulonglong2 c = xB[u][r];

                unsigned long long acc[NJ];
#pragma unroll
                for (int j = 0; j < NJ; ++j) {
                    acc[j] = 0ull;
                    ffma2(acc[j], a.x, wA[j].x);
                    ffma2(acc[j], a.y, wA[j].y);
                    ffma2(acc[j], c.x, wB[j].x);
                    ffma2(acc[j], c.y, wB[j].y);
                }

                // Accumulator-halving butterfly on u64 (f32x2 adds).
                {
                    const bool h4 = (lane & 16) != 0;
#pragma unroll
                    for (int k = 0; k < 8; ++k) {
                        unsigned long long send = h4 ? acc[k] : acc[k + 8];
                        unsigned long long keep = h4 ? acc[k + 8] : acc[k];
                        acc[k] = add2(keep, __shfl_xor_sync(0xffffffffu, send, 16));
                    }
                    const bool h3 = (lane & 8) != 0;
#pragma unroll
                    for (int k = 0; k < 4; ++k) {
                        unsigned long long send = h3 ? acc[k] : acc[k + 4];
                        unsigned long long keep = h3 ? acc[k + 4] : acc[k];
                        acc[k] = add2(keep, __shfl_xor_sync(0xffffffffu, send, 8));
                    }
                    const bool h2 = (lane & 4) != 0;
#pragma unroll
                    for (int k = 0; k < 2; ++k) {
                        unsigned long long send = h2 ? acc[k] : acc[k + 2];
                        unsigned long long keep = h2 ? acc[k + 2] : acc[k];
                        acc[k] = add2(keep, __shfl_xor_sync(0xffffffffu, send, 4));
                    }
                    const bool h1 = (lane & 2) != 0;
                    {
                        unsigned long long send = h1 ? acc[0] : acc[1];
                        unsigned long long keep = h1 ? acc[1] : acc[0];
                        acc[0] = add2(keep, __shfl_xor_sync(0xffffffffu, send, 2));
                    }
                    acc[0] = add2(acc[0], __shfl_xor_sync(0xffffffffu, acc[0], 1));
                }

                if (n < NNODE && (lane & 1) == 0) {
                    float lo, hi;
                    asm("mov.b64 {%0, %1}, %2;" : "=f"(lo), "=f"(hi) : "l"(acc[0]));
                    gs[(size_t)n * NJ + (lane >> 1)] = lo + hi;
                }
            }
        }
    }
#undef LOADROW
}

// ---------------------------------------------------------------------------
// Kernel 3: edge gather + sigmoid, 4 edges per thread (int4/float4).
//   Indices are int32; node = idx>>3, h = idx&7.
// ---------------------------------------------------------------------------
__device__ __forceinline__ float edge_score(int hidx, int tidx) {
    const float s = g_scores[(size_t)(hidx >> 3) * NJ + (hidx & 7)] +
                    g_scores[(size_t)(tidx >> 3) * NJ + 8 + (tidx & 7)];
    return 1.0f / (1.0f + __expf(-s));
}

__global__ void gather_kernel(const int4* __restrict__ head4,
                              const int4* __restrict__ tail4,
                              float4* __restrict__ out4, int total4) {
    const int i = blockIdx.x * blockDim.x + threadIdx.x;
    if (i >= total4) return;
    const int4 h = head4[i];
    const int4 t = tail4[i];
    float4 o;
    o.x = edge_score(h.x, t.x);
    o.y = edge_score(h.y, t.y);
    o.z = edge_score(h.z, t.z);
    o.w = edge_score(h.w, t.w);
    out4[i] = o;
}

// ---------------------------------------------------------------------------
extern "C" void kernel_launch(void* const* d_in, const int* in_sizes, int n_in,
                              void* d_out, int out_size) {
    // Classify inputs by element count — robust to metadata ordering.
    const float* x    = nullptr;
    const float* W    = nullptr;
    const int*   head = nullptr;
    const int*   tail = nullptr;
    const float* ssrc = nullptr;
    const float* strg = nullptr;
    for (int i = 0; i < n_in; ++i) {
        const int sz = in_sizes[i];
        if (sz == BSZ * NNODE * FIN) {
            x = (const float*)d_in[i];
        } else if (sz == NH * ND * FIN) {
            W = (const float*)d_in[i];
        } else if (sz == BSZ * EDG) {
            if (!head) head = (const int*)d_in[i];
            else       tail = (const int*)d_in[i];
        } else if (sz == BSZ * NH * ND) {
            if (!ssrc) ssrc = (const float*)d_in[i];
            else       strg = (const float*)d_in[i];
        }
    }
    float* out = (float*)d_out;  // [8,160000] f32

    build_w_kernel<<<BSZ * NJ, FIN>>>(W, ssrc, strg);

    dim3 g2(18, BSZ);   // 144 blocks: exactly one wave on 148 SMs
    score_kernel<<<g2, 256>>>(x);

    const int total4 = BSZ * EDG / 4;   // 320000
    gather_kernel<<<(total4 + 255) / 256, 256>>>(
        (const int4*)head, (const int4*)tail, (float4*)out, total4);
}

// round 13
// speedup vs baseline: 2.1300x; 1.3122x over previous
#include <cuda_runtime.h>
#include <cuda_bf16.h>
#include <cstdint>

#define BSZ   8
#define NNODE 20000
#define FIN   256
#define NH    8
#define ND    64
#define EDG   160000
#define NJ    16

__device__ __align__(16) float g_w[BSZ * NJ * FIN];         // effective weights (f32)
__device__ __align__(16) float g_scores[BSZ * NNODE * NJ];  // per-node scores

// ---------------------------------------------------------------------------
// Kernel 1: fold scoring vectors into projection weights.
//   g_w[b][j][f] = sum_d W[(h*64+d)*256+f] * s[b][h][d]
// ---------------------------------------------------------------------------
__global__ void build_w_kernel(const float* __restrict__ W,
                               const float* __restrict__ ssrc,
                               const float* __restrict__ strg) {
    __shared__ float4 part[4][64];
    const int tid = threadIdx.x;
    const int f4  = tid & 63;
    const int dg  = tid >> 6;
    const int bj  = blockIdx.x;      // 0..127
    const int b   = bj >> 4;
    const int j   = bj & 15;
    const int h   = j & 7;
    const float* __restrict__ s = (j < 8 ? ssrc : strg) + (b * NH + h) * ND;
    const float4* __restrict__ W4 = (const float4*)W;

    float4 acc = make_float4(0.f, 0.f, 0.f, 0.f);
#pragma unroll
    for (int k = 0; k < 16; ++k) {
        const int d = dg * 16 + k;
        const float4 w = W4[(h * ND + d) * 64 + f4];
        const float sv = __ldg(&s[d]);
        acc.x += w.x * sv; acc.y += w.y * sv; acc.z += w.z * sv; acc.w += w.w * sv;
    }
    part[dg][f4] = acc;
    __syncthreads();
    if (tid < 64) {
        float4 a = part[0][tid], b2 = part[1][tid], c = part[2][tid], d2 = part[3][tid];
        float4 r;
        r.x = (a.x + b2.x) + (c.x + d2.x);
        r.y = (a.y + b2.y) + (c.y + d2.y);
        r.z = (a.z + b2.z) + (c.z + d2.z);
        r.w = (a.w + b2.w) + (c.w + d2.w);
        ((float4*)g_w)[bj * 64 + tid] = r;
    }
}

// ---------------------------------------------------------------------------
// Kernel 2: scoring via warp-level mma.sync (bf16 hi/lo split, fp32 accum).
//   One warp per 16-row M-block; K=256 (16 chunks of k16); N=16 (2 n-tiles).
//   score = Ahi*Bhi + Ahi*Blo + Alo*Bhi   (lo*lo dropped, ~2^-32 rel)
// ---------------------------------------------------------------------------

// Pack two floats (f0 -> low half, f1 -> high half) to bf16x2; return residual floats.
__device__ __forceinline__ void split2(float f0, float f1,
                                       uint32_t& hi, float& r0, float& r1) {
    asm("cvt.rn.bf16x2.f32 %0, %1, %2;" : "=r"(hi) : "f"(f1), "f"(f0));
    r0 = f0 - __uint_as_float(hi << 16);
    r1 = f1 - __uint_as_float(hi & 0xFFFF0000u);
}
__device__ __forceinline__ uint32_t pack2(float f0, float f1) {
    uint32_t p;
    asm("cvt.rn.bf16x2.f32 %0, %1, %2;" : "=r"(p) : "f"(f1), "f"(f0));
    return p;
}
__device__ __forceinline__ void mma16816(float* c, const uint32_t* a,
                                         uint32_t b0, uint32_t b1) {
    asm volatile(
        "mma.sync.aligned.m16n8k16.row.col.f32.bf16.bf16.f32 "
        "{%0,%1,%2,%3}, {%4,%5,%6,%7}, {%8,%9}, {%0,%1,%2,%3};"
        : "+f"(c[0]), "+f"(c[1]), "+f"(c[2]), "+f"(c[3])
        : "r"(a[0]), "r"(a[1]), "r"(a[2]), "r"(a[3]), "r"(b0), "r"(b1));
}

#define WSTRIDE 264   // bf16 elements per weight row in smem (pad -> conflict-free)

__global__ __launch_bounds__(256)
void score_mma_kernel(const float* __restrict__ x) {
    // smem weights: [split hi/lo][16 n][264 k] bf16
    __shared__ __align__(16) __nv_bfloat16 smw[2][NJ][WSTRIDE];

    const int tid  = threadIdx.x;
    const int warp = tid >> 5;
    const int lane = tid & 31;
    const int b    = blockIdx.y;
    const int row0 = blockIdx.x * 128 + warp * 16;

    // ---- build B (hi/lo bf16) in smem: 1024 float4s over 256 threads ----
    {
        const float4* __restrict__ w4 = (const float4*)(g_w + b * NJ * FIN);
#pragma unroll
        for (int i = 0; i < 4; ++i) {
            const int lin = i * 256 + tid;   // 0..1023
            const int n   = lin >> 6;        // 0..15
            const int k4  = lin & 63;        // float4 index along K
            const float4 v = w4[n * 64 + k4];
            uint32_t h01, h23;
            float r0, r1, r2, r3;
            split2(v.x, v.y, h01, r0, r1);
            split2(v.z, v.w, h23, r2, r3);
            uint32_t l01 = pack2(r0, r1);
            uint32_t l23 = pack2(r2, r3);
            uint32_t* ph = (uint32_t*)&smw[0][n][k4 * 4];
            uint32_t* pl = (uint32_t*)&smw[1][n][k4 * 4];
            ph[0] = h01; ph[1] = h23;
            pl[0] = l01; pl[1] = l23;
        }
    }
    __syncthreads();
    if (row0 >= NNODE) return;

    const float* __restrict__ xb = x + (size_t)b * NNODE * FIN;
    const int rA = row0 + (lane >> 2);       // fragment row
    const int rB = rA + 8;
    const int kc = (lane & 3) * 2;           // fragment k within chunk
    const int nB = lane >> 2;                // fragment n within n-tile

    float acc0[4] = {0.f, 0.f, 0.f, 0.f};    // n-tile 0 (cols 0..7)
    float acc1[4] = {0.f, 0.f, 0.f, 0.f};    // n-tile 1 (cols 8..15)

#pragma unroll
    for (int ch = 0; ch < 16; ++ch) {
        const int k0 = ch * 16;
        // A fragment: 4 float2 loads
        const float2 fa0 = *(const float2*)&xb[(size_t)rA * FIN + k0 + kc];
        const float2 fa1 = *(const float2*)&xb[(size_t)rB * FIN + k0 + kc];
        const float2 fa2 = *(const float2*)&xb[(size_t)rA * FIN + k0 + 8 + kc];
        const float2 fa3 = *(const float2*)&xb[(size_t)rB * FIN + k0 + 8 + kc];

        uint32_t ah[4], al[4];
        {
            float r0, r1;
            split2(fa0.x, fa0.y, ah[0], r0, r1); al[0] = pack2(r0, r1);
            split2(fa1.x, fa1.y, ah[1], r0, r1); al[1] = pack2(r0, r1);
            split2(fa2.x, fa2.y, ah[2], r0, r1); al[2] = pack2(r0, r1);
            split2(fa3.x, fa3.y, ah[3], r0, r1); al[3] = pack2(r0, r1);
        }

        // B fragments from smem (conflict-free via WSTRIDE pad)
        const uint32_t bh00 = *(const uint32_t*)&smw[0][nB][k0 + kc];
        const uint32_t bh01 = *(const uint32_t*)&smw[0][nB][k0 + 8 + kc];
        const uint32_t bh10 = *(const uint32_t*)&smw[0][8 + nB][k0 + kc];
        const uint32_t bh11 = *(const uint32_t*)&smw[0][8 + nB][k0 + 8 + kc];
        const uint32_t bl00 = *(const uint32_t*)&smw[1][nB][k0 + kc];
        const uint32_t bl01 = *(const uint32_t*)&smw[1][nB][k0 + 8 + kc];
        const uint32_t bl10 = *(const uint32_t*)&smw[1][8 + nB][k0 + kc];
        const uint32_t bl11 = *(const uint32_t*)&smw[1][8 + nB][k0 + 8 + kc];

        mma16816(acc0, ah, bh00, bh01);   // hi*hi, n-tile 0
        mma16816(acc1, ah, bh10, bh11);   // hi*hi, n-tile 1
        mma16816(acc0, ah, bl00, bl01);   // hi*lo
        mma16816(acc1, ah, bl10, bl11);
        mma16816(acc0, al, bh00, bh01);   // lo*hi
        mma16816(acc1, al, bh10, bh11);
    }

    // C fragment store: c0,c1 -> row lane>>2, cols (lane&3)*2+{0,1}; c2,c3 -> row+8
    float* __restrict__ gs = g_scores + ((size_t)b * NNODE) * NJ;
    const int crow0 = row0 + (lane >> 2);
    const int crow1 = crow0 + 8;
    const int ccol  = (lane & 3) * 2;
    *(float2*)&gs[(size_t)crow0 * NJ + ccol]     = make_float2(acc0[0], acc0[1]);
    *(float2*)&gs[(size_t)crow1 * NJ + ccol]     = make_float2(acc0[2], acc0[3]);
    *(float2*)&gs[(size_t)crow0 * NJ + 8 + ccol] = make_float2(acc1[0], acc1[1]);
    *(float2*)&gs[(size_t)crow1 * NJ + 8 + ccol] = make_float2(acc1[2], acc1[3]);
}

// ---------------------------------------------------------------------------
// Kernel 3: edge gather + sigmoid, 4 edges per thread.
// ---------------------------------------------------------------------------
__device__ __forceinline__ float edge_score(int hidx, int tidx) {
    const float s = g_scores[(size_t)(hidx >> 3) * NJ + (hidx & 7)] +
                    g_scores[(size_t)(tidx >> 3) * NJ + 8 + (tidx & 7)];
    return 1.0f / (1.0f + __expf(-s));
}

__global__ void gather_kernel(const int4* __restrict__ head4,
                              const int4* __restrict__ tail4,
                              float4* __restrict__ out4, int total4) {
    const int i = blockIdx.x * blockDim.x + threadIdx.x;
    if (i >= total4) return;
    const int4 h = head4[i];
    const int4 t = tail4[i];
    float4 o;
    o.x = edge_score(h.x, t.x);
    o.y = edge_score(h.y, t.y);
    o.z = edge_score(h.z, t.z);
    o.w = edge_score(h.w, t.w);
    out4[i] = o;
}

// ---------------------------------------------------------------------------
extern "C" void kernel_launch(void* const* d_in, const int* in_sizes, int n_in,
                              void* d_out, int out_size) {
    const float* x    = nullptr;
    const float* W    = nullptr;
    const int*   head = nullptr;
    const int*   tail = nullptr;
    const float* ssrc = nullptr;
    const float* strg = nullptr;
    for (int i = 0; i < n_in; ++i) {
        const int sz = in_sizes[i];
        if (sz == BSZ * NNODE * FIN) {
            x = (const float*)d_in[i];
        } else if (sz == NH * ND * FIN) {
            W = (const float*)d_in[i];
        } else if (sz == BSZ * EDG) {
            if (!head) head = (const int*)d_in[i];
            else       tail = (const int*)d_in[i];
        } else if (sz == BSZ * NH * ND) {
            if (!ssrc) ssrc = (const float*)d_in[i];
            else       strg = (const float*)d_in[i];
        }
    }
    float* out = (float*)d_out;

    build_w_kernel<<<BSZ * NJ, 256>>>(W, ssrc, strg);

    dim3 g2(157, BSZ);   // 157*128 = 20096 rows covered; tail warps guard
    score_mma_kernel<<<g2, 256>>>(x);

    const int total4 = BSZ * EDG / 4;
    gather_kernel<<<(total4 + 255) / 256, 256>>>(
        (const int4*)head, (const int4*)tail, (float4*)out, total4);
}

// round 14
// speedup vs baseline: 2.5995x; 1.2204x over previous
#include <cuda_runtime.h>
#include <cuda_bf16.h>
#include <cstdint>

#define BSZ   8
#define NNODE 20000
#define FIN   256
#define NH    8
#define ND    64
#define EDG   160000
#define NJ    16

__device__ __align__(16) float g_w[BSZ * NJ * FIN];         // effective weights (f32)
__device__ __align__(16) float g_scores[BSZ * NNODE * NJ];  // per-node scores

// ---------------------------------------------------------------------------
// Kernel 1: fold scoring vectors into projection weights.
//   g_w[b][j][f] = sum_d W[(h*64+d)*256+f] * s[b][h][d]
// ---------------------------------------------------------------------------
__global__ void build_w_kernel(const float* __restrict__ W,
                               const float* __restrict__ ssrc,
                               const float* __restrict__ strg) {
    __shared__ float4 part[4][64];
    const int tid = threadIdx.x;
    const int f4  = tid & 63;
    const int dg  = tid >> 6;
    const int bj  = blockIdx.x;      // 0..127
    const int b   = bj >> 4;
    const int j   = bj & 15;
    const int h   = j & 7;
    const float* __restrict__ s = (j < 8 ? ssrc : strg) + (b * NH + h) * ND;
    const float4* __restrict__ W4 = (const float4*)W;

    float4 acc = make_float4(0.f, 0.f, 0.f, 0.f);
#pragma unroll
    for (int k = 0; k < 16; ++k) {
        const int d = dg * 16 + k;
        const float4 w = W4[(h * ND + d) * 64 + f4];
        const float sv = __ldg(&s[d]);
        acc.x += w.x * sv; acc.y += w.y * sv; acc.z += w.z * sv; acc.w += w.w * sv;
    }
    part[dg][f4] = acc;
    __syncthreads();
    if (tid < 64) {
        float4 a = part[0][tid], b2 = part[1][tid], c = part[2][tid], d2 = part[3][tid];
        float4 r;
        r.x = (a.x + b2.x) + (c.x + d2.x);
        r.y = (a.y + b2.y) + (c.y + d2.y);
        r.z = (a.z + b2.z) + (c.z + d2.z);
        r.w = (a.w + b2.w) + (c.w + d2.w);
        ((float4*)g_w)[bj * 64 + tid] = r;
    }
}

// ---------------------------------------------------------------------------
// Kernel 2: scoring via warp-level mma.sync (bf16 hi/lo split, fp32 accum).
//   One warp per 16-row M-block; K=256 (16 chunks of k16); N=16 (2 n-tiles).
//   score = Ahi*Bhi + Ahi*Blo + Alo*Bhi   (lo*lo dropped, ~2^-32 rel)
//
// K-PERMUTATION: within each k16 chunk, thread c=(lane&3) owns logical
// k ∈ {4c..4c+3} (instead of the native {2c,2c+1,2c+8,2c+9}).  MMA sums over
// k, so any per-chunk permutation applied to BOTH A and B fragments is exact.
// Payoff: the A fragment per row is ONE float4 -> 2x LDG.128 per chunk
// (halves LSU issue vs 4x LDG.64).  B is permuted at smem-WRITE time only;
// the mainloop LDS pattern is unchanged.
// ---------------------------------------------------------------------------
__device__ __forceinline__ void split2(float f0, float f1,
                                       uint32_t& hi, float& r0, float& r1) {
    asm("cvt.rn.bf16x2.f32 %0, %1, %2;" : "=r"(hi) : "f"(f1), "f"(f0));
    r0 = f0 - __uint_as_float(hi << 16);
    r1 = f1 - __uint_as_float(hi & 0xFFFF0000u);
}
__device__ __forceinline__ uint32_t pack2(float f0, float f1) {
    uint32_t p;
    asm("cvt.rn.bf16x2.f32 %0, %1, %2;" : "=r"(p) : "f"(f1), "f"(f0));
    return p;
}
__device__ __forceinline__ void mma16816(float* c, const uint32_t* a,
                                         uint32_t b0, uint32_t b1) {
    asm volatile(
        "mma.sync.aligned.m16n8k16.row.col.f32.bf16.bf16.f32 "
        "{%0,%1,%2,%3}, {%4,%5,%6,%7}, {%8,%9}, {%0,%1,%2,%3};"
        : "+f"(c[0]), "+f"(c[1]), "+f"(c[2]), "+f"(c[3])
        : "r"(a[0]), "r"(a[1]), "r"(a[2]), "r"(a[3]), "r"(b0), "r"(b1));
}

#define WSTRIDE 264   // bf16 elements per weight row in smem (pad -> conflict-free)

__global__ __launch_bounds__(256)
void score_mma_kernel(const float* __restrict__ x) {
    // smem weights: [split hi/lo][16 n][264 k] bf16, k stored PERMUTED per chunk
    __shared__ __align__(16) __nv_bfloat16 smw[2][NJ][WSTRIDE];

    const int tid  = threadIdx.x;
    const int warp = tid >> 5;
    const int lane = tid & 31;
    const int b    = blockIdx.y;
    const int row0 = blockIdx.x * 128 + warp * 16;

    // ---- build B (hi/lo bf16, k-permuted) : 1024 float4s over 256 threads ----
    {
        const float4* __restrict__ w4 = (const float4*)(g_w + b * NJ * FIN);
#pragma unroll
        for (int i = 0; i < 4; ++i) {
            const int lin = i * 256 + tid;   // 0..1023
            const int n   = lin >> 6;        // 0..15
            const int k4  = lin & 63;        // float4 index along K (logical k = 4*k4..)
            const int ch  = k4 >> 2;         // k16 chunk
            const int c   = k4 & 3;          // owner thread within chunk
            const int k0  = ch * 16;
            const float4 v = w4[n * 64 + k4];
            uint32_t h01, h23;
            float r0, r1, r2, r3;
            split2(v.x, v.y, h01, r0, r1);
            split2(v.z, v.w, h23, r2, r3);
            const uint32_t l01 = pack2(r0, r1);
            const uint32_t l23 = pack2(r2, r3);
            // physical slots: {4c,4c+1} -> k0+2c ; {4c+2,4c+3} -> k0+8+2c
            *(uint32_t*)&smw[0][n][k0 + 2 * c]     = h01;
            *(uint32_t*)&smw[0][n][k0 + 8 + 2 * c] = h23;
            *(uint32_t*)&smw[1][n][k0 + 2 * c]     = l01;
            *(uint32_t*)&smw[1][n][k0 + 8 + 2 * c] = l23;
        }
    }
    __syncthreads();
    if (row0 >= NNODE) return;

    const float* __restrict__ xb = x + (size_t)b * NNODE * FIN;
    const int rA = row0 + (lane >> 2);       // fragment row
    const int rB = rA + 8;
    const int c4 = (lane & 3) * 4;           // this thread's logical k base in chunk
    const int kc = (lane & 3) * 2;           // physical B slot offset
    const int nB = lane >> 2;                // fragment n within n-tile

    const float* __restrict__ pA = xb + (size_t)rA * FIN + c4;
    const float* __restrict__ pB = xb + (size_t)rB * FIN + c4;

    float acc0[4] = {0.f, 0.f, 0.f, 0.f};    // n-tile 0 (cols 0..7)
    float acc1[4] = {0.f, 0.f, 0.f, 0.f};    // n-tile 1 (cols 8..15)

#pragma unroll
    for (int ch = 0; ch < 16; ++ch) {
        const int k0 = ch * 16;
        // A fragment: ONE float4 per row (streaming hint keeps scores in L2)
        const float4 fa = __ldcs((const float4*)(pA + k0));
        const float4 fb = __ldcs((const float4*)(pB + k0));

        uint32_t ah[4], al[4];
        {
            float r0, r1;
            split2(fa.x, fa.y, ah[0], r0, r1); al[0] = pack2(r0, r1);
            split2(fb.x, fb.y, ah[1], r0, r1); al[1] = pack2(r0, r1);
            split2(fa.z, fa.w, ah[2], r0, r1); al[2] = pack2(r0, r1);
            split2(fb.z, fb.w, ah[3], r0, r1); al[3] = pack2(r0, r1);
        }

        // B fragments from smem (physical layout already matches)
        const uint32_t bh00 = *(const uint32_t*)&smw[0][nB][k0 + kc];
        const uint32_t bh01 = *(const uint32_t*)&smw[0][nB][k0 + 8 + kc];
        const uint32_t bh10 = *(const uint32_t*)&smw[0][8 + nB][k0 + kc];
        const uint32_t bh11 = *(const uint32_t*)&smw[0][8 + nB][k0 + 8 + kc];
        const uint32_t bl00 = *(const uint32_t*)&smw[1][nB][k0 + kc];
        const uint32_t bl01 = *(const uint32_t*)&smw[1][nB][k0 + 8 + kc];
        const uint32_t bl10 = *(const uint32_t*)&smw[1][8 + nB][k0 + kc];
        const uint32_t bl11 = *(const uint32_t*)&smw[1][8 + nB][k0 + 8 + kc];

        mma16816(acc0, ah, bh00, bh01);   // hi*hi, n-tile 0
        mma16816(acc1, ah, bh10, bh11);   // hi*hi, n-tile 1
        mma16816(acc0, ah, bl00, bl01);   // hi*lo
        mma16816(acc1, ah, bl10, bl11);
        mma16816(acc0, al, bh00, bh01);   // lo*hi
        mma16816(acc1, al, bh10, bh11);
    }

    // C fragment store
    float* __restrict__ gs = g_scores + ((size_t)b * NNODE) * NJ;
    const int crow0 = row0 + (lane >> 2);
    const int crow1 = crow0 + 8;
    const int ccol  = (lane & 3) * 2;
    *(float2*)&gs[(size_t)crow0 * NJ + ccol]     = make_float2(acc0[0], acc0[1]);
    *(float2*)&gs[(size_t)crow1 * NJ + ccol]     = make_float2(acc0[2], acc0[3]);
    *(float2*)&gs[(size_t)crow0 * NJ + 8 + ccol] = make_float2(acc1[0], acc1[1]);
    *(float2*)&gs[(size_t)crow1 * NJ + 8 + ccol] = make_float2(acc1[2], acc1[3]);
}

// ---------------------------------------------------------------------------
// Kernel 3: edge gather + sigmoid, 4 edges per thread.
// ---------------------------------------------------------------------------
__device__ __forceinline__ float edge_score(int hidx, int tidx) {
    const float s = g_scores[(size_t)(hidx >> 3) * NJ + (hidx & 7)] +
                    g_scores[(size_t)(tidx >> 3) * NJ + 8 + (tidx & 7)];
    return 1.0f / (1.0f + __expf(-s));
}

__global__ void gather_kernel(const int4* __restrict__ head4,
                              const int4* __restrict__ tail4,
                              float4* __restrict__ out4, int total4) {
    const int i = blockIdx.x * blockDim.x + threadIdx.x;
    if (i >= total4) return;
    const int4 h = head4[i];
    const int4 t = tail4[i];
    float4 o;
    o.x = edge_score(h.x, t.x);
    o.y = edge_score(h.y, t.y);
    o.z = edge_score(h.z, t.z);
    o.w = edge_score(h.w, t.w);
    out4[i] = o;
}

// ---------------------------------------------------------------------------
extern "C" void kernel_launch(void* const* d_in, const int* in_sizes, int n_in,
                              void* d_out, int out_size) {
    const float* x    = nullptr;
    const float* W    = nullptr;
    const int*   head = nullptr;
    const int*   tail = nullptr;
    const float* ssrc = nullptr;
    const float* strg = nullptr;
    for (int i = 0; i < n_in; ++i) {
        const int sz = in_sizes[i];
        if (sz == BSZ * NNODE * FIN) {
            x = (const float*)d_in[i];
        } else if (sz == NH * ND * FIN) {
            W = (const float*)d_in[i];
        } else if (sz == BSZ * EDG) {
            if (!head) head = (const int*)d_in[i];
            else       tail = (const int*)d_in[i];
        } else if (sz == BSZ * NH * ND) {
            if (!ssrc) ssrc = (const float*)d_in[i];
            else       strg = (const float*)d_in[i];
        }
    }
    float* out = (float*)d_out;

    build_w_kernel<<<BSZ * NJ, 256>>>(W, ssrc, strg);

    dim3 g2(157, BSZ);   // 157*128 = 20096 rows covered; tail warps guard
    score_mma_kernel<<<g2, 256>>>(x);

    const int total4 = BSZ * EDG / 4;
    gather_kernel<<<(total4 + 255) / 256, 256>>>(
        (const int4*)head, (const int4*)tail, (float4*)out, total4);
}